// round 2
// baseline (speedup 1.0000x reference)
#include <cuda_runtime.h>
#include <cuda_bf16.h>

#define NN 100000
#define NE 1600000
#define NGR 16
#define DD 64
#define SCAN_CH 500
#define SCAN_NB 200   // 200 * 500 = 100000

// ---------------- scratch (static device arrays; no allocation) ----------------
__device__ int    g_deg[NN];
__device__ int    g_cur[NN];
__device__ int    g_rowptr[NN + 1];
__device__ float  g_dinv[NN];
__device__ int    g_srcs[NE];
__device__ float  g_buf0[NN * DD];
__device__ float  g_buf1[NN * DD];
__device__ double g_pool[NGR * DD];
__device__ int    g_pcnt[NGR];
__device__ int    g_bsum[256];
__device__ int    g_is64;   // 1 if edge_index/batch are int64, 0 if int32

// ---------------- dtype detection -----------------------------------------------
// int64 values < 2^31 have zero high words (odd 32-bit word indices, little-endian).
// int32 index data has real (almost surely nonzero) values there.
// Reads first 8192 words = 32 KB, in-bounds for both layouts (int32 buffer: 12.8 MB).
__global__ void k_detect(const unsigned int* __restrict__ w) {
    __shared__ unsigned int s;
    if (threadIdx.x == 0) s = 0u;
    __syncthreads();
    unsigned int o = 0u;
    for (int i = 1 + 2 * threadIdx.x; i < 8192; i += 2 * blockDim.x) o |= w[i];
    atomicOr(&s, o);
    __syncthreads();
    if (threadIdx.x == 0) g_is64 = (s == 0u) ? 1 : 0;
}

__device__ __forceinline__ int load_idx(const void* p, long long i, int is64) {
    return is64 ? (int)((const long long*)p)[i] : ((const int*)p)[i];
}

// ---------------- init ----------------
__global__ void k_init() {
    int i = blockIdx.x * blockDim.x + threadIdx.x;
    if (i < NN) { g_deg[i] = 0; g_cur[i] = 0; }
    if (i < NGR * DD) g_pool[i] = 0.0;
    if (i < NGR) g_pcnt[i] = 0;
    if (i == 0) g_rowptr[NN] = NE;
}

// ---------------- degree histogram over dst ----------------
__global__ void k_hist(const void* __restrict__ ei) {
    int e = blockIdx.x * blockDim.x + threadIdx.x;
    if (e < NE) {
        int d = load_idx(ei, (long long)NE + e, g_is64);
        atomicAdd(&g_deg[d], 1);
    }
}

// ---------------- dinv = rsqrt(indeg + 1)  (self-loop included) ----------------
__global__ void k_dinv() {
    int i = blockIdx.x * blockDim.x + threadIdx.x;
    if (i < NN) g_dinv[i] = rsqrtf((float)(g_deg[i] + 1));
}

// ---------------- scan step A: per-chunk sums ----------------
__global__ void k_bsum() {
    __shared__ int ssum[256];
    int b = blockIdx.x;
    int base = b * SCAN_CH;
    int s = 0;
    for (int j = threadIdx.x; j < SCAN_CH; j += 256) {
        int idx = base + j;
        if (idx < NN) s += g_deg[idx];
    }
    ssum[threadIdx.x] = s;
    __syncthreads();
    for (int o = 128; o > 0; o >>= 1) {
        if (threadIdx.x < o) ssum[threadIdx.x] += ssum[threadIdx.x + o];
        __syncthreads();
    }
    if (threadIdx.x == 0) g_bsum[b] = ssum[0];
}

// ---------------- scan step B: exclusive scan of chunk sums (1 block) ----------
__global__ void k_scanb() {
    __shared__ int sh[256];
    int t = threadIdx.x;
    int v = (t < SCAN_NB) ? g_bsum[t] : 0;
    sh[t] = v;
    __syncthreads();
    for (int o = 1; o < 256; o <<= 1) {
        int x = sh[t];
        int y = (t >= o) ? sh[t - o] : 0;
        __syncthreads();
        sh[t] = x + y;
        __syncthreads();
    }
    if (t < SCAN_NB) g_bsum[t] = sh[t] - v;  // exclusive prefix
}

// ---------------- scan step C: row_ptr ----------------
__global__ void k_rowptr() {
    __shared__ int sh[128];
    int b = blockIdx.x, t = threadIdx.x;
    int base = b * SCAN_CH;
    int i0 = base + t * 4;
    int d0 = 0, d1 = 0, d2 = 0, d3 = 0;
    if (t < 125) {  // 125*4 = 500
        if (i0 + 0 < NN) d0 = g_deg[i0 + 0];
        if (i0 + 1 < NN) d1 = g_deg[i0 + 1];
        if (i0 + 2 < NN) d2 = g_deg[i0 + 2];
        if (i0 + 3 < NN) d3 = g_deg[i0 + 3];
    }
    int s = d0 + d1 + d2 + d3;
    sh[t] = s;
    __syncthreads();
    int v = s;
    for (int o = 1; o < 128; o <<= 1) {
        int x = sh[t];
        int y = (t >= o) ? sh[t - o] : 0;
        __syncthreads();
        sh[t] = x + y;
        __syncthreads();
    }
    int excl = sh[t] - v + g_bsum[b];
    if (t < 125) {
        if (i0 + 0 < NN) g_rowptr[i0 + 0] = excl;
        if (i0 + 1 < NN) g_rowptr[i0 + 1] = excl + d0;
        if (i0 + 2 < NN) g_rowptr[i0 + 2] = excl + d0 + d1;
        if (i0 + 3 < NN) g_rowptr[i0 + 3] = excl + d0 + d1 + d2;
    }
}

// ---------------- scatter edges into CSR slots ----------------
__global__ void k_scatter(const void* __restrict__ ei) {
    int e = blockIdx.x * blockDim.x + threadIdx.x;
    if (e < NE) {
        int is64 = g_is64;
        int d = load_idx(ei, (long long)NE + e, is64);
        int s = load_idx(ei, e, is64);
        int slot = g_rowptr[d] + atomicAdd(&g_cur[d], 1);
        g_srcs[slot] = s;
    }
}

// ---------------- dense transform: out[i,:] = (in[i,:] @ W) * dinv[i] ----------
// Block: 256 threads = 8 warps. Warps (r, r+4) cover row r of a 4-row chunk,
// warp>>2 selects column half. Each thread caches one W column in registers.
__global__ void __launch_bounds__(256) k_transform(const float* __restrict__ in,
                                                   const float* __restrict__ W,
                                                   float* __restrict__ out) {
    __shared__ float xs[4][DD];
    __shared__ float sdinv[4];
    int warp = threadIdx.x >> 5;
    int lane = threadIdx.x & 31;
    int r = warp & 3;
    int col = ((warp >> 2) << 5) + lane;  // 0..63
    float w[DD];
#pragma unroll
    for (int k = 0; k < DD; k++) w[k] = W[k * DD + col];

    for (int row0 = blockIdx.x * 4; row0 < NN; row0 += gridDim.x * 4) {
        int t = threadIdx.x;
        int rr = row0 + (t >> 6);
        if (rr < NN) xs[t >> 6][t & 63] = in[rr * DD + (t & 63)];
        if (t < 4 && row0 + t < NN) sdinv[t] = g_dinv[row0 + t];
        __syncthreads();
        int row = row0 + r;
        if (row < NN) {
            float acc0 = 0.f, acc1 = 0.f;
#pragma unroll
            for (int k = 0; k < DD; k += 2) {
                acc0 = fmaf(xs[r][k], w[k], acc0);
                acc1 = fmaf(xs[r][k + 1], w[k + 1], acc1);
            }
            out[row * DD + col] = (acc0 + acc1) * sdinv[r];
        }
        __syncthreads();
    }
}

// ---------------- aggregation: warp per dst node --------------------------------
// out[d,:] = act( dinv[d] * (hs[d,:] + sum_{s in in(d)} hs[s,:]) + b )
template <int RELU>
__global__ void __launch_bounds__(256) k_agg(const float* __restrict__ hs,
                                             const float* __restrict__ bias,
                                             float* __restrict__ out) {
    int gw = (blockIdx.x * blockDim.x + threadIdx.x) >> 5;
    if (gw >= NN) return;
    int lane = threadIdx.x & 31;
    int node = gw;
    const float2* __restrict__ hp = (const float2*)hs;

    float2 acc = hp[node * 32 + lane];  // self-loop term
    float ax2 = 0.f, ay2 = 0.f;
    int beg = g_rowptr[node];
    int end = g_rowptr[node + 1];
    int i = beg;
    for (; i + 4 <= end; i += 4) {
        int s0 = g_srcs[i + 0];
        int s1 = g_srcs[i + 1];
        int s2 = g_srcs[i + 2];
        int s3 = g_srcs[i + 3];
        float2 v0 = hp[s0 * 32 + lane];
        float2 v1 = hp[s1 * 32 + lane];
        float2 v2 = hp[s2 * 32 + lane];
        float2 v3 = hp[s3 * 32 + lane];
        acc.x += v0.x; acc.y += v0.y;
        ax2 += v1.x;   ay2 += v1.y;
        acc.x += v2.x; acc.y += v2.y;
        ax2 += v3.x;   ay2 += v3.y;
    }
    for (; i < end; i++) {
        int s = g_srcs[i];
        float2 v = hp[s * 32 + lane];
        acc.x += v.x; acc.y += v.y;
    }
    acc.x += ax2; acc.y += ay2;

    float dv = g_dinv[node];
    float ox = fmaf(acc.x, dv, bias[lane * 2 + 0]);
    float oy = fmaf(acc.y, dv, bias[lane * 2 + 1]);
    if (RELU) { ox = fmaxf(ox, 0.f); oy = fmaxf(oy, 0.f); }
    ((float2*)out)[node * 32 + lane] = make_float2(ox, oy);
}

// ---------------- pooling: warp per contiguous node range (batch is sorted) -----
#define POOL_WARPS 800
#define POOL_SPAN 125  // 800 * 125 = 100000
__global__ void k_pool(const float* __restrict__ h,
                       const void* __restrict__ batch) {
    int gw = (blockIdx.x * blockDim.x + threadIdx.x) >> 5;
    int lane = threadIdx.x & 31;
    int n0 = gw * POOL_SPAN;
    if (n0 >= NN) return;
    int n1 = n0 + POOL_SPAN;
    if (n1 > NN) n1 = NN;
    const float2* __restrict__ hp = (const float2*)h;
    int is64 = g_is64;

    int g = load_idx(batch, n0, is64);
    float sx = 0.f, sy = 0.f;
    int cnt = 0;
    for (int n = n0; n < n1; n++) {
        int gn = load_idx(batch, n, is64);
        if (gn != g) {
            atomicAdd(&g_pool[g * DD + lane * 2 + 0], (double)sx);
            atomicAdd(&g_pool[g * DD + lane * 2 + 1], (double)sy);
            if (lane == 0) atomicAdd(&g_pcnt[g], cnt);
            sx = 0.f; sy = 0.f; cnt = 0; g = gn;
        }
        float2 v = hp[n * 32 + lane];
        sx += v.x; sy += v.y; cnt++;
    }
    atomicAdd(&g_pool[g * DD + lane * 2 + 0], (double)sx);
    atomicAdd(&g_pool[g * DD + lane * 2 + 1], (double)sy);
    if (lane == 0) atomicAdd(&g_pcnt[g], cnt);
}

// ---------------- finalize ----------------
__global__ void k_final(float* __restrict__ out) {
    int i = blockIdx.x * blockDim.x + threadIdx.x;
    if (i < NGR * DD) {
        int g = i >> 6;
        int c = g_pcnt[g];
        double denom = (double)(c > 1 ? c : 1);
        out[i] = (float)(g_pool[i] / denom);
    }
}

// ---------------- launch ----------------
extern "C" void kernel_launch(void* const* d_in, const int* in_sizes, int n_in,
                              void* d_out, int out_size) {
    const float* x  = (const float*)d_in[0];
    const float* W1 = (const float*)d_in[1];
    const float* b1 = (const float*)d_in[2];
    const float* W2 = (const float*)d_in[3];
    const float* b2 = (const float*)d_in[4];
    const void*  ei = d_in[5];      // (2, NE) row-major, int32 OR int64 (detected)
    const void*  batch = d_in[6];   // (NN,), same int width as ei
    float* out = (float*)d_out;

    float* buf0;  cudaGetSymbolAddress((void**)&buf0, g_buf0);
    float* buf1;  cudaGetSymbolAddress((void**)&buf1, g_buf1);

    k_detect<<<1, 256>>>((const unsigned int*)ei);
    k_init<<<(NN + 255) / 256, 256>>>();
    k_hist<<<(NE + 255) / 256, 256>>>(ei);
    k_dinv<<<(NN + 255) / 256, 256>>>();
    k_bsum<<<SCAN_NB, 256>>>();
    k_scanb<<<1, 256>>>();
    k_rowptr<<<SCAN_NB, 128>>>();
    k_scatter<<<(NE + 255) / 256, 256>>>(ei);

    // layer 1
    k_transform<<<1184, 256>>>(x, W1, buf0);
    k_agg<1><<<(NN * 32 + 255) / 256, 256>>>(buf0, b1, buf1);
    // layer 2
    k_transform<<<1184, 256>>>(buf1, W2, buf0);
    k_agg<0><<<(NN * 32 + 255) / 256, 256>>>(buf0, b2, buf1);

    k_pool<<<POOL_WARPS * 32 / 256, 256>>>(buf1, batch);
    k_final<<<1, 1024>>>(out);
}

// round 5
// speedup vs baseline: 1.0051x; 1.0051x over previous
#include <cuda_runtime.h>
#include <cuda_bf16.h>

#define NN 100000
#define NE 1600000
#define NGR 16
#define DD 64
#define SCAN_CH 500
#define SCAN_NB 200   // 200 * 500 = 100000

// ---------------- scratch (static device arrays; no allocation) ----------------
__device__ int    g_deg[NN];
__device__ int    g_cur[NN];
__device__ int    g_rowptr[NN + 1];
__device__ float  g_dinv[NN];
__device__ int    g_srcs[NE];
__device__ float  g_buf0[NN * DD];
__device__ float  g_buf1[NN * DD];
__device__ double g_pool[NGR * DD];
__device__ int    g_pcnt[NGR];
__device__ int    g_bsum[256];
__device__ int    g_is64;   // 1 if edge_index/batch are int64, 0 if int32

// ---------------- packed f32x2 helpers (sm_100+) --------------------------------
__device__ __forceinline__ unsigned long long f2pack(float x, float y) {
    unsigned long long r;
    asm("mov.b64 %0, {%1, %2};" : "=l"(r) : "f"(x), "f"(y));
    return r;
}
__device__ __forceinline__ void f2unpack(unsigned long long v, float& x, float& y) {
    asm("mov.b64 {%0, %1}, %2;" : "=f"(x), "=f"(y) : "l"(v));
}
__device__ __forceinline__ unsigned long long ffma2(unsigned long long a,
                                                    unsigned long long b,
                                                    unsigned long long c) {
    unsigned long long d;
    asm("fma.rn.f32x2 %0, %1, %2, %3;" : "=l"(d) : "l"(a), "l"(b), "l"(c));
    return d;
}

// ---------------- dtype detection + init ----------------------------------------
// int64 values < 2^31 have zero high words (odd 32-bit word indices, little-endian).
// Reads first 8192 words = 32 KB, in-bounds for both layouts.
__global__ void k_detect_init(const unsigned int* __restrict__ w) {
    int i = blockIdx.x * blockDim.x + threadIdx.x;
    if (i < NN) { g_deg[i] = 0; g_cur[i] = 0; }
    if (i < NGR * DD) g_pool[i] = 0.0;
    if (i < NGR) g_pcnt[i] = 0;
    if (i == 0) g_rowptr[NN] = NE;
    if (blockIdx.x == 0) {
        __shared__ unsigned int s;
        if (threadIdx.x == 0) s = 0u;
        __syncthreads();
        unsigned int o = 0u;
        for (int j = 1 + 2 * threadIdx.x; j < 8192; j += 2 * blockDim.x) o |= w[j];
        atomicOr(&s, o);
        __syncthreads();
        if (threadIdx.x == 0) g_is64 = (s == 0u) ? 1 : 0;
    }
}

__device__ __forceinline__ int load_idx(const void* p, long long i, int is64) {
    return is64 ? (int)((const long long*)p)[i] : ((const int*)p)[i];
}

// ---------------- degree histogram over dst ----------------
__global__ void k_hist(const void* __restrict__ ei) {
    int e = blockIdx.x * blockDim.x + threadIdx.x;
    if (e < NE) {
        int d = load_idx(ei, (long long)NE + e, g_is64);
        atomicAdd(&g_deg[d], 1);
    }
}

// ---------------- per-chunk sums + dinv (fused) ----------------
__global__ void k_bsum_dinv() {
    __shared__ int ssum[256];
    int b = blockIdx.x;
    int base = b * SCAN_CH;
    int s = 0;
    for (int j = threadIdx.x; j < SCAN_CH; j += 256) {
        int idx = base + j;
        if (idx < NN) {
            int d = g_deg[idx];
            s += d;
            g_dinv[idx] = rsqrtf((float)(d + 1));
        }
    }
    ssum[threadIdx.x] = s;
    __syncthreads();
    for (int o = 128; o > 0; o >>= 1) {
        if (threadIdx.x < o) ssum[threadIdx.x] += ssum[threadIdx.x + o];
        __syncthreads();
    }
    if (threadIdx.x == 0) g_bsum[b] = ssum[0];
}

// ---------------- exclusive scan of chunk sums (1 block) ----------
__global__ void k_scanb() {
    __shared__ int sh[256];
    int t = threadIdx.x;
    int v = (t < SCAN_NB) ? g_bsum[t] : 0;
    sh[t] = v;
    __syncthreads();
    for (int o = 1; o < 256; o <<= 1) {
        int x = sh[t];
        int y = (t >= o) ? sh[t - o] : 0;
        __syncthreads();
        sh[t] = x + y;
        __syncthreads();
    }
    if (t < SCAN_NB) g_bsum[t] = sh[t] - v;  // exclusive prefix
}

// ---------------- row_ptr ----------------
__global__ void k_rowptr() {
    __shared__ int sh[128];
    int b = blockIdx.x, t = threadIdx.x;
    int base = b * SCAN_CH;
    int i0 = base + t * 4;
    int d0 = 0, d1 = 0, d2 = 0, d3 = 0;
    if (t < 125) {  // 125*4 = 500
        if (i0 + 0 < NN) d0 = g_deg[i0 + 0];
        if (i0 + 1 < NN) d1 = g_deg[i0 + 1];
        if (i0 + 2 < NN) d2 = g_deg[i0 + 2];
        if (i0 + 3 < NN) d3 = g_deg[i0 + 3];
    }
    int s = d0 + d1 + d2 + d3;
    sh[t] = s;
    __syncthreads();
    int v = s;
    for (int o = 1; o < 128; o <<= 1) {
        int x = sh[t];
        int y = (t >= o) ? sh[t - o] : 0;
        __syncthreads();
        sh[t] = x + y;
        __syncthreads();
    }
    int excl = sh[t] - v + g_bsum[b];
    if (t < 125) {
        if (i0 + 0 < NN) g_rowptr[i0 + 0] = excl;
        if (i0 + 1 < NN) g_rowptr[i0 + 1] = excl + d0;
        if (i0 + 2 < NN) g_rowptr[i0 + 2] = excl + d0 + d1;
        if (i0 + 3 < NN) g_rowptr[i0 + 3] = excl + d0 + d1 + d2;
    }
}

// ---------------- scatter edges into CSR slots ----------------
__global__ void k_scatter(const void* __restrict__ ei) {
    int e = blockIdx.x * blockDim.x + threadIdx.x;
    if (e < NE) {
        int is64 = g_is64;
        int d = load_idx(ei, (long long)NE + e, is64);
        int s = load_idx(ei, e, is64);
        int slot = g_rowptr[d] + atomicAdd(&g_cur[d], 1);
        g_srcs[slot] = s;
    }
}

// ---------------- dense transform: out[i,:] = (in[i,:] @ W) * dinv[i] ----------
// 256 threads = 8 warps. Warps (r, r+4) cover row r of a 4-row chunk, warp>>2
// selects column half. Each thread caches one W column as 32 packed f32x2 regs.
// Inner product via fma.rn.f32x2: 32 FFMA2 per row-col instead of 64 FFMA.
__global__ void __launch_bounds__(256) k_transform(const float* __restrict__ in,
                                                   const float* __restrict__ W,
                                                   float* __restrict__ out) {
    __shared__ float xs[4][DD];
    __shared__ float sdinv[4];
    int warp = threadIdx.x >> 5;
    int lane = threadIdx.x & 31;
    int r = warp & 3;
    int col = ((warp >> 2) << 5) + lane;  // 0..63
    unsigned long long w2[DD / 2];
#pragma unroll
    for (int k = 0; k < DD / 2; k++)
        w2[k] = f2pack(W[(2 * k) * DD + col], W[(2 * k + 1) * DD + col]);

    for (int row0 = blockIdx.x * 4; row0 < NN; row0 += gridDim.x * 4) {
        int t = threadIdx.x;
        int rr = row0 + (t >> 6);
        if (rr < NN) xs[t >> 6][t & 63] = in[rr * DD + (t & 63)];
        if (t < 4 && row0 + t < NN) sdinv[t] = g_dinv[row0 + t];
        __syncthreads();
        int row = row0 + r;
        if (row < NN) {
            const float4* xr = (const float4*)xs[r];
            unsigned long long acc0 = f2pack(0.f, 0.f);
            unsigned long long acc1 = f2pack(0.f, 0.f);
#pragma unroll
            for (int q = 0; q < DD / 4; q++) {
                float4 xv = xr[q];
                acc0 = ffma2(f2pack(xv.x, xv.y), w2[2 * q + 0], acc0);
                acc1 = ffma2(f2pack(xv.z, xv.w), w2[2 * q + 1], acc1);
            }
            float a, b, c, d;
            f2unpack(acc0, a, b);
            f2unpack(acc1, c, d);
            out[row * DD + col] = ((a + b) + (c + d)) * sdinv[r];
        }
        __syncthreads();
    }
}

// ---------------- aggregation: warp per dst node --------------------------------
// out[d,:] = act( dinv[d] * (hs[d,:] + sum_{s in in(d)} hs[s,:]) + b )
// 8-deep gather unroll: 8 outstanding LDG.64 per warp, 4 accumulator pairs.
template <int RELU>
__global__ void __launch_bounds__(256) k_agg(const float* __restrict__ hs,
                                             const float* __restrict__ bias,
                                             float* __restrict__ out) {
    int gw = (blockIdx.x * blockDim.x + threadIdx.x) >> 5;
    if (gw >= NN) return;
    int lane = threadIdx.x & 31;
    int node = gw;
    const float2* __restrict__ hp = (const float2*)hs;

    float2 a0 = hp[node * 32 + lane];  // self-loop term
    float2 a1 = make_float2(0.f, 0.f);
    float2 a2 = make_float2(0.f, 0.f);
    float2 a3 = make_float2(0.f, 0.f);
    int beg = g_rowptr[node];
    int end = g_rowptr[node + 1];
    int i = beg;
    for (; i + 8 <= end; i += 8) {
        int s0 = g_srcs[i + 0], s1 = g_srcs[i + 1];
        int s2 = g_srcs[i + 2], s3 = g_srcs[i + 3];
        int s4 = g_srcs[i + 4], s5 = g_srcs[i + 5];
        int s6 = g_srcs[i + 6], s7 = g_srcs[i + 7];
        float2 v0 = hp[s0 * 32 + lane];
        float2 v1 = hp[s1 * 32 + lane];
        float2 v2 = hp[s2 * 32 + lane];
        float2 v3 = hp[s3 * 32 + lane];
        float2 v4 = hp[s4 * 32 + lane];
        float2 v5 = hp[s5 * 32 + lane];
        float2 v6 = hp[s6 * 32 + lane];
        float2 v7 = hp[s7 * 32 + lane];
        a0.x += v0.x; a0.y += v0.y;  a1.x += v1.x; a1.y += v1.y;
        a2.x += v2.x; a2.y += v2.y;  a3.x += v3.x; a3.y += v3.y;
        a0.x += v4.x; a0.y += v4.y;  a1.x += v5.x; a1.y += v5.y;
        a2.x += v6.x; a2.y += v6.y;  a3.x += v7.x; a3.y += v7.y;
    }
    for (; i + 2 <= end; i += 2) {
        int s0 = g_srcs[i + 0], s1 = g_srcs[i + 1];
        float2 v0 = hp[s0 * 32 + lane];
        float2 v1 = hp[s1 * 32 + lane];
        a0.x += v0.x; a0.y += v0.y;
        a1.x += v1.x; a1.y += v1.y;
    }
    if (i < end) {
        int s = g_srcs[i];
        float2 v = hp[s * 32 + lane];
        a2.x += v.x; a2.y += v.y;
    }
    float accx = (a0.x + a1.x) + (a2.x + a3.x);
    float accy = (a0.y + a1.y) + (a2.y + a3.y);

    float dv = g_dinv[node];
    float ox = fmaf(accx, dv, bias[lane * 2 + 0]);
    float oy = fmaf(accy, dv, bias[lane * 2 + 1]);
    if (RELU) { ox = fmaxf(ox, 0.f); oy = fmaxf(oy, 0.f); }
    ((float2*)out)[node * 32 + lane] = make_float2(ox, oy);
}

// ---------------- pooling: warp per contiguous node range (batch is sorted) -----
#define POOL_WARPS 800
#define POOL_SPAN 125  // 800 * 125 = 100000
__global__ void k_pool(const float* __restrict__ h,
                       const void* __restrict__ batch) {
    int gw = (blockIdx.x * blockDim.x + threadIdx.x) >> 5;
    int lane = threadIdx.x & 31;
    int n0 = gw * POOL_SPAN;
    if (n0 >= NN) return;
    int n1 = n0 + POOL_SPAN;
    if (n1 > NN) n1 = NN;
    const float2* __restrict__ hp = (const float2*)h;
    int is64 = g_is64;

    int g = load_idx(batch, n0, is64);
    float sx = 0.f, sy = 0.f;
    int cnt = 0;
    for (int n = n0; n < n1; n++) {
        int gn = load_idx(batch, n, is64);
        if (gn != g) {
            atomicAdd(&g_pool[g * DD + lane * 2 + 0], (double)sx);
            atomicAdd(&g_pool[g * DD + lane * 2 + 1], (double)sy);
            if (lane == 0) atomicAdd(&g_pcnt[g], cnt);
            sx = 0.f; sy = 0.f; cnt = 0; g = gn;
        }
        float2 v = hp[n * 32 + lane];
        sx += v.x; sy += v.y; cnt++;
    }
    atomicAdd(&g_pool[g * DD + lane * 2 + 0], (double)sx);
    atomicAdd(&g_pool[g * DD + lane * 2 + 1], (double)sy);
    if (lane == 0) atomicAdd(&g_pcnt[g], cnt);
}

// ---------------- finalize ----------------
__global__ void k_final(float* __restrict__ out) {
    int i = blockIdx.x * blockDim.x + threadIdx.x;
    if (i < NGR * DD) {
        int g = i >> 6;
        int c = g_pcnt[g];
        double denom = (double)(c > 1 ? c : 1);
        out[i] = (float)(g_pool[i] / denom);
    }
}

// ---------------- launch ----------------
extern "C" void kernel_launch(void* const* d_in, const int* in_sizes, int n_in,
                              void* d_out, int out_size) {
    const float* x  = (const float*)d_in[0];
    const float* W1 = (const float*)d_in[1];
    const float* b1 = (const float*)d_in[2];
    const float* W2 = (const float*)d_in[3];
    const float* b2 = (const float*)d_in[4];
    const void*  ei = d_in[5];      // (2, NE) row-major, int32 OR int64 (detected)
    const void*  batch = d_in[6];   // (NN,), same int width as ei
    float* out = (float*)d_out;

    float* buf0;  cudaGetSymbolAddress((void**)&buf0, g_buf0);
    float* buf1;  cudaGetSymbolAddress((void**)&buf1, g_buf1);

    k_detect_init<<<(NN + 255) / 256, 256>>>((const unsigned int*)ei);
    k_hist<<<(NE + 255) / 256, 256>>>(ei);
    k_bsum_dinv<<<SCAN_NB, 256>>>();
    k_scanb<<<1, 256>>>();
    k_rowptr<<<SCAN_NB, 128>>>();
    k_scatter<<<(NE + 255) / 256, 256>>>(ei);

    // layer 1
    k_transform<<<1184, 256>>>(x, W1, buf0);
    k_agg<1><<<(NN * 32 + 255) / 256, 256>>>(buf0, b1, buf1);
    // layer 2
    k_transform<<<1184, 256>>>(buf1, W2, buf0);
    k_agg<0><<<(NN * 32 + 255) / 256, 256>>>(buf0, b2, buf1);

    k_pool<<<POOL_WARPS * 32 / 256, 256>>>(buf1, batch);
    k_final<<<1, 1024>>>(out);
}

// round 6
// speedup vs baseline: 1.0154x; 1.0102x over previous
#include <cuda_runtime.h>
#include <cuda_fp16.h>

#define NN 100000
#define NE 1600000
#define NGR 16
#define DD 64
#define SCAN_CH 500
#define SCAN_NB 200   // 200 * 500 = 100000

// ---------------- scratch (static device arrays; no allocation) ----------------
__device__ int    g_deg[NN];
__device__ int    g_cur[NN];
__device__ int    g_rowptr[NN + 1];
__device__ float  g_dinv[NN];
__device__ int    g_srcs[NE];
__device__ __half g_h16a[NN * DD];   // transform outputs (dinv folded), gathered
__device__ __half g_h16b[NN * DD];   // agg1 activations (layer-2 transform input)
__device__ float  g_buf1[NN * DD];   // agg2 output (fp32, pooled)
__device__ double g_pool[NGR * DD];
__device__ int    g_pcnt[NGR];
__device__ int    g_bsum[256];
__device__ int    g_is64;   // 1 if edge_index/batch are int64, 0 if int32

// ---------------- packed f32x2 helpers (sm_100+) --------------------------------
__device__ __forceinline__ unsigned long long f2pack(float x, float y) {
    unsigned long long r;
    asm("mov.b64 %0, {%1, %2};" : "=l"(r) : "f"(x), "f"(y));
    return r;
}
__device__ __forceinline__ void f2unpack(unsigned long long v, float& x, float& y) {
    asm("mov.b64 {%0, %1}, %2;" : "=f"(x), "=f"(y) : "l"(v));
}
__device__ __forceinline__ unsigned long long ffma2(unsigned long long a,
                                                    unsigned long long b,
                                                    unsigned long long c) {
    unsigned long long d;
    asm("fma.rn.f32x2 %0, %1, %2, %3;" : "=l"(d) : "l"(a), "l"(b), "l"(c));
    return d;
}

// ---------------- dtype detection + init ----------------------------------------
__global__ void k_detect_init(const unsigned int* __restrict__ w) {
    int i = blockIdx.x * blockDim.x + threadIdx.x;
    if (i < NN) { g_deg[i] = 0; g_cur[i] = 0; }
    if (i < NGR * DD) g_pool[i] = 0.0;
    if (i < NGR) g_pcnt[i] = 0;
    if (i == 0) g_rowptr[NN] = NE;
    if (blockIdx.x == 0) {
        __shared__ unsigned int s;
        if (threadIdx.x == 0) s = 0u;
        __syncthreads();
        unsigned int o = 0u;
        for (int j = 1 + 2 * threadIdx.x; j < 8192; j += 2 * blockDim.x) o |= w[j];
        atomicOr(&s, o);
        __syncthreads();
        if (threadIdx.x == 0) g_is64 = (s == 0u) ? 1 : 0;
    }
}

__device__ __forceinline__ int load_idx(const void* p, long long i, int is64) {
    return is64 ? (int)((const long long*)p)[i] : ((const int*)p)[i];
}

// ---------------- degree histogram over dst ----------------
__global__ void k_hist(const void* __restrict__ ei) {
    int e = blockIdx.x * blockDim.x + threadIdx.x;
    if (e < NE) {
        int d = load_idx(ei, (long long)NE + e, g_is64);
        atomicAdd(&g_deg[d], 1);
    }
}

// ---------------- per-chunk sums + dinv (fused) ----------------
__global__ void k_bsum_dinv() {
    __shared__ int ssum[256];
    int b = blockIdx.x;
    int base = b * SCAN_CH;
    int s = 0;
    for (int j = threadIdx.x; j < SCAN_CH; j += 256) {
        int idx = base + j;
        if (idx < NN) {
            int d = g_deg[idx];
            s += d;
            g_dinv[idx] = rsqrtf((float)(d + 1));
        }
    }
    ssum[threadIdx.x] = s;
    __syncthreads();
    for (int o = 128; o > 0; o >>= 1) {
        if (threadIdx.x < o) ssum[threadIdx.x] += ssum[threadIdx.x + o];
        __syncthreads();
    }
    if (threadIdx.x == 0) g_bsum[b] = ssum[0];
}

// ---------------- row_ptr (inlines the 200-chunk exclusive scan) ----------------
__global__ void __launch_bounds__(256) k_rowptr() {
    __shared__ int sb[256];
    __shared__ int sh[256];
    int t = threadIdx.x, b = blockIdx.x;
    // every block redundantly scans the 200 chunk sums (800B, trivially cheap)
    int v = (t < SCAN_NB) ? g_bsum[t] : 0;
    sb[t] = v;
    __syncthreads();
    for (int o = 1; o < 256; o <<= 1) {
        int x = sb[t];
        int y = (t >= o) ? sb[t - o] : 0;
        __syncthreads();
        sb[t] = x + y;
        __syncthreads();
    }
    int chunk_off = (b > 0) ? sb[b - 1] : 0;

    // per-chunk exclusive scan of 500 degrees (125 active threads x 4)
    int base = b * SCAN_CH;
    int i0 = base + t * 4;
    int d0 = 0, d1 = 0, d2 = 0, d3 = 0;
    if (t < 125) {
        if (i0 + 0 < NN) d0 = g_deg[i0 + 0];
        if (i0 + 1 < NN) d1 = g_deg[i0 + 1];
        if (i0 + 2 < NN) d2 = g_deg[i0 + 2];
        if (i0 + 3 < NN) d3 = g_deg[i0 + 3];
    }
    int s = d0 + d1 + d2 + d3;
    sh[t] = s;
    __syncthreads();
    for (int o = 1; o < 256; o <<= 1) {
        int x = sh[t];
        int y = (t >= o) ? sh[t - o] : 0;
        __syncthreads();
        sh[t] = x + y;
        __syncthreads();
    }
    int excl = sh[t] - s + chunk_off;
    if (t < 125) {
        if (i0 + 0 < NN) g_rowptr[i0 + 0] = excl;
        if (i0 + 1 < NN) g_rowptr[i0 + 1] = excl + d0;
        if (i0 + 2 < NN) g_rowptr[i0 + 2] = excl + d0 + d1;
        if (i0 + 3 < NN) g_rowptr[i0 + 3] = excl + d0 + d1 + d2;
    }
}

// ---------------- scatter edges into CSR slots ----------------
__global__ void k_scatter(const void* __restrict__ ei) {
    int e = blockIdx.x * blockDim.x + threadIdx.x;
    if (e < NE) {
        int is64 = g_is64;
        int d = load_idx(ei, (long long)NE + e, is64);
        int s = load_idx(ei, e, is64);
        int slot = g_rowptr[d] + atomicAdd(&g_cur[d], 1);
        g_srcs[slot] = s;
    }
}

// ---------------- dense transform: out[i,:] = fp16( (in[i,:] @ W) * dinv[i] ) ---
// 256 threads = 8 warps. Warps (r, r+4) cover row r of a 4-row chunk, warp>>2
// selects column half. Each thread caches one W column as 32 packed f32x2 regs.
template <typename Tin>
__global__ void __launch_bounds__(256) k_transform(const Tin* __restrict__ in,
                                                   const float* __restrict__ W,
                                                   __half* __restrict__ out) {
    __shared__ float xs[4][DD];
    __shared__ float sdinv[4];
    int warp = threadIdx.x >> 5;
    int lane = threadIdx.x & 31;
    int r = warp & 3;
    int col = ((warp >> 2) << 5) + lane;  // 0..63
    unsigned long long w2[DD / 2];
#pragma unroll
    for (int k = 0; k < DD / 2; k++)
        w2[k] = f2pack(W[(2 * k) * DD + col], W[(2 * k + 1) * DD + col]);

    for (int row0 = blockIdx.x * 4; row0 < NN; row0 += gridDim.x * 4) {
        int t = threadIdx.x;
        int rr = row0 + (t >> 6);
        if (rr < NN) xs[t >> 6][t & 63] = (float)in[rr * DD + (t & 63)];
        if (t < 4 && row0 + t < NN) sdinv[t] = g_dinv[row0 + t];
        __syncthreads();
        int row = row0 + r;
        if (row < NN) {
            const float4* xr = (const float4*)xs[r];
            unsigned long long acc0 = f2pack(0.f, 0.f);
            unsigned long long acc1 = f2pack(0.f, 0.f);
#pragma unroll
            for (int q = 0; q < DD / 4; q++) {
                float4 xv = xr[q];
                acc0 = ffma2(f2pack(xv.x, xv.y), w2[2 * q + 0], acc0);
                acc1 = ffma2(f2pack(xv.z, xv.w), w2[2 * q + 1], acc1);
            }
            float a, b, c, d;
            f2unpack(acc0, a, b);
            f2unpack(acc1, c, d);
            out[row * DD + col] = __float2half(((a + b) + (c + d)) * sdinv[r]);
        }
        __syncthreads();
    }
}

// ---------------- aggregation: warp per dst node --------------------------------
// stored[s] = dinv[s] * (h W)[s]  (fp16). out[d] = act(dinv[d]*(sum stored[s]
// over in-edges + stored[d]) + b).  agg1 -> fp16 out, agg2 -> fp32 out.
template <int RELU, typename Tout>
__global__ void __launch_bounds__(256) k_agg(const __half2* __restrict__ hp,
                                             const float* __restrict__ bias,
                                             Tout* __restrict__ out) {
    int gw = (blockIdx.x * blockDim.x + threadIdx.x) >> 5;
    if (gw >= NN) return;
    int lane = threadIdx.x & 31;
    int node = gw;

    float2 sv = __half22float2(hp[node * 32 + lane]);  // self term stored[d]
    float2 a0 = sv;
    float2 a1 = make_float2(0.f, 0.f);
    float2 a2 = make_float2(0.f, 0.f);
    float2 a3 = make_float2(0.f, 0.f);
    int beg = g_rowptr[node];
    int end = g_rowptr[node + 1];
    int i = beg;
    for (; i + 8 <= end; i += 8) {
        int s0 = g_srcs[i + 0], s1 = g_srcs[i + 1];
        int s2 = g_srcs[i + 2], s3 = g_srcs[i + 3];
        int s4 = g_srcs[i + 4], s5 = g_srcs[i + 5];
        int s6 = g_srcs[i + 6], s7 = g_srcs[i + 7];
        float2 v0 = __half22float2(hp[s0 * 32 + lane]);
        float2 v1 = __half22float2(hp[s1 * 32 + lane]);
        float2 v2 = __half22float2(hp[s2 * 32 + lane]);
        float2 v3 = __half22float2(hp[s3 * 32 + lane]);
        float2 v4 = __half22float2(hp[s4 * 32 + lane]);
        float2 v5 = __half22float2(hp[s5 * 32 + lane]);
        float2 v6 = __half22float2(hp[s6 * 32 + lane]);
        float2 v7 = __half22float2(hp[s7 * 32 + lane]);
        a0.x += v0.x; a0.y += v0.y;  a1.x += v1.x; a1.y += v1.y;
        a2.x += v2.x; a2.y += v2.y;  a3.x += v3.x; a3.y += v3.y;
        a0.x += v4.x; a0.y += v4.y;  a1.x += v5.x; a1.y += v5.y;
        a2.x += v6.x; a2.y += v6.y;  a3.x += v7.x; a3.y += v7.y;
    }
    for (; i + 2 <= end; i += 2) {
        int s0 = g_srcs[i + 0], s1 = g_srcs[i + 1];
        float2 v0 = __half22float2(hp[s0 * 32 + lane]);
        float2 v1 = __half22float2(hp[s1 * 32 + lane]);
        a0.x += v0.x; a0.y += v0.y;
        a1.x += v1.x; a1.y += v1.y;
    }
    if (i < end) {
        int s = g_srcs[i];
        float2 v = __half22float2(hp[s * 32 + lane]);
        a2.x += v.x; a2.y += v.y;
    }
    float accx = (a0.x + a1.x) + (a2.x + a3.x);
    float accy = (a0.y + a1.y) + (a2.y + a3.y);

    float dv = g_dinv[node];
    float ox = fmaf(accx, dv, bias[lane * 2 + 0]);
    float oy = fmaf(accy, dv, bias[lane * 2 + 1]);
    if (RELU) { ox = fmaxf(ox, 0.f); oy = fmaxf(oy, 0.f); }
    if (sizeof(Tout) == 2) {
        ((__half2*)out)[node * 32 + lane] = __float22half2_rn(make_float2(ox, oy));
    } else {
        ((float2*)out)[node * 32 + lane] = make_float2(ox, oy);
    }
}

// ---------------- pooling: warp per contiguous node range (batch is sorted) -----
#define POOL_WARPS 800
#define POOL_SPAN 125  // 800 * 125 = 100000
__global__ void k_pool(const float* __restrict__ h,
                       const void* __restrict__ batch) {
    int gw = (blockIdx.x * blockDim.x + threadIdx.x) >> 5;
    int lane = threadIdx.x & 31;
    int n0 = gw * POOL_SPAN;
    if (n0 >= NN) return;
    int n1 = n0 + POOL_SPAN;
    if (n1 > NN) n1 = NN;
    const float2* __restrict__ hp = (const float2*)h;
    int is64 = g_is64;

    int g = load_idx(batch, n0, is64);
    float sx = 0.f, sy = 0.f;
    int cnt = 0;
    for (int n = n0; n < n1; n++) {
        int gn = load_idx(batch, n, is64);
        if (gn != g) {
            atomicAdd(&g_pool[g * DD + lane * 2 + 0], (double)sx);
            atomicAdd(&g_pool[g * DD + lane * 2 + 1], (double)sy);
            if (lane == 0) atomicAdd(&g_pcnt[g], cnt);
            sx = 0.f; sy = 0.f; cnt = 0; g = gn;
        }
        float2 v = hp[n * 32 + lane];
        sx += v.x; sy += v.y; cnt++;
    }
    atomicAdd(&g_pool[g * DD + lane * 2 + 0], (double)sx);
    atomicAdd(&g_pool[g * DD + lane * 2 + 1], (double)sy);
    if (lane == 0) atomicAdd(&g_pcnt[g], cnt);
}

// ---------------- finalize ----------------
__global__ void k_final(float* __restrict__ out) {
    int i = blockIdx.x * blockDim.x + threadIdx.x;
    if (i < NGR * DD) {
        int g = i >> 6;
        int c = g_pcnt[g];
        double denom = (double)(c > 1 ? c : 1);
        out[i] = (float)(g_pool[i] / denom);
    }
}

// ---------------- launch ----------------
extern "C" void kernel_launch(void* const* d_in, const int* in_sizes, int n_in,
                              void* d_out, int out_size) {
    const float* x  = (const float*)d_in[0];
    const float* W1 = (const float*)d_in[1];
    const float* b1 = (const float*)d_in[2];
    const float* W2 = (const float*)d_in[3];
    const float* b2 = (const float*)d_in[4];
    const void*  ei = d_in[5];      // (2, NE) row-major, int32 OR int64 (detected)
    const void*  batch = d_in[6];   // (NN,), same int width as ei
    float* out = (float*)d_out;

    __half* h16a; cudaGetSymbolAddress((void**)&h16a, g_h16a);
    __half* h16b; cudaGetSymbolAddress((void**)&h16b, g_h16b);
    float*  buf1; cudaGetSymbolAddress((void**)&buf1, g_buf1);

    k_detect_init<<<(NN + 255) / 256, 256>>>((const unsigned int*)ei);
    k_hist<<<(NE + 255) / 256, 256>>>(ei);
    k_bsum_dinv<<<SCAN_NB, 256>>>();
    k_rowptr<<<SCAN_NB, 256>>>();
    k_scatter<<<(NE + 255) / 256, 256>>>(ei);

    // layer 1
    k_transform<float><<<1184, 256>>>(x, W1, h16a);
    k_agg<1, __half><<<(NN * 32 + 255) / 256, 256>>>((const __half2*)h16a, b1, h16b);
    // layer 2
    k_transform<__half><<<1184, 256>>>(h16b, W2, h16a);
    k_agg<0, float><<<(NN * 32 + 255) / 256, 256>>>((const __half2*)h16a, b2, buf1);

    k_pool<<<POOL_WARPS * 32 / 256, 256>>>(buf1, batch);
    k_final<<<1, 1024>>>(out);
}